// round 17
// baseline (speedup 1.0000x reference)
#include <cuda_runtime.h>
#include <cuda_fp16.h>
#include <cuda_fp8.h>
#include <cstdint>

#define BSZ   128
#define NIN   784
#define NHID  1024
#define NOUT  10
#define TT    200
#define NPAIR (TT * BSZ)          // 25600
#define ALPHA 0.05f
#define KPAD8 896                  // 7 * 128 (K padded, fp8 bytes)
#define NCH8  7                    // K chunks of 128

// -------------------- scratch (static device globals) ---------------------
__device__ uint8_t        g_A8[(size_t)NPAIR * KPAD8];  // e4m3 spikes (pair, k)
__device__ uint8_t        g_B8[(size_t)NHID * KPAD8];   // e4m3 relu(w1)^T (n, k)
__device__ unsigned short g_Ih[(size_t)NPAIR * NHID];   // fp16 I_h (pair, h)
__device__ float          g_part[(size_t)BSZ * TT * NOUT]; // neg sums (b,t,o)
__device__ float          g_colsum[NOUT];               // sum_h relu(w2[h][o])

// --------------------------------------------------------------------------
// kA: stage spikes as e4m3 A8[(t*B+b), i]. Spikes are {0,1}: 1.0 = 0x38
// exactly. 128-input byte tiles (25.7KB), uint32-packed 128B row stores.
// --------------------------------------------------------------------------
__global__ void __launch_bounds__(256) kA_stage(const float* __restrict__ sp) {
    __shared__ uint8_t tile[128][201];
    const int b = blockIdx.x;
    const int i0 = blockIdx.y * 128;
    for (int l = threadIdx.x; l < 128 * 200; l += 256) {
        int ii = l / 200, t = l - ii * 200;
        int i = i0 + ii;
        float v = (i < NIN) ? sp[((size_t)b * NIN + i) * TT + t] : 0.0f;
        tile[ii][t] = (v > 0.5f) ? 0x38 : 0x00;   // e4m3 1.0 / 0.0
    }
    __syncthreads();
    for (int l = threadIdx.x; l < 200 * 32; l += 256) {
        int t = l >> 5, q = l & 31;
        uint32_t w = (uint32_t)tile[4 * q + 0][t]
                   | ((uint32_t)tile[4 * q + 1][t] << 8)
                   | ((uint32_t)tile[4 * q + 2][t] << 16)
                   | ((uint32_t)tile[4 * q + 3][t] << 24);
        *reinterpret_cast<uint32_t*>(g_A8 + ((size_t)t * BSZ + b) * KPAD8 + i0 + 4 * q) = w;
    }
}

// --------------------------------------------------------------------------
// kB: stage relu(w1)^T as e4m3 B8[n, i]. y==7 blocks zero g_part; (0,7)
// also reduces colsum(relu(w2)).
// --------------------------------------------------------------------------
__global__ void __launch_bounds__(256) kB_stage(const float* __restrict__ w1,
                                                const float* __restrict__ w2) {
    if (blockIdx.y == 7) {
        const int base = (blockIdx.x * 256 + threadIdx.x) * 4;
        for (int idx = base; idx < BSZ * TT * NOUT; idx += 32 * 256 * 4)
            *reinterpret_cast<float4*>(g_part + idx) = make_float4(0.f, 0.f, 0.f, 0.f);
        if (blockIdx.x == 0) {
            __shared__ float cs[NOUT];
            const int tid = threadIdx.x;
            if (tid < NOUT) cs[tid] = 0.0f;
            __syncthreads();
            float part[NOUT];
            #pragma unroll
            for (int o = 0; o < NOUT; o++) part[o] = 0.0f;
            for (int h = tid; h < NHID; h += 256) {
                #pragma unroll
                for (int o = 0; o < NOUT; o++)
                    part[o] += fmaxf(w2[(size_t)h * NOUT + o], 0.0f);
            }
            #pragma unroll
            for (int o = 0; o < NOUT; o++) atomicAdd(cs + o, part[o]);
            __syncthreads();
            if (tid < NOUT) g_colsum[tid] = cs[tid];
        }
        return;
    }
    // 128-i x 32-n tile per block: transpose via SMEM, byte stores
    __shared__ float tile[32][129];
    const int n0 = blockIdx.x * 32;
    const int i0 = blockIdx.y * 128;
    for (int l = threadIdx.x; l < 128 * 32; l += 256) {
        int ii = l >> 5, c = l & 31;
        int i = i0 + ii;
        tile[c][ii] = (i < NIN) ? fmaxf(w1[(size_t)i * NHID + n0 + c], 0.0f) : 0.0f;
    }
    __syncthreads();
    for (int l = threadIdx.x; l < 32 * 32; l += 256) {
        int cc = l >> 5, q = l & 31;
        uint32_t w = 0;
        #pragma unroll
        for (int j = 0; j < 4; j++) {
            uint8_t byte = __nv_cvt_float_to_fp8(tile[cc][4 * q + j],
                                                 __NV_SATFINITE, __NV_E4M3);
            w |= (uint32_t)byte << (8 * j);
        }
        *reinterpret_cast<uint32_t*>(g_B8 + (size_t)(n0 + cc) * KPAD8 + i0 + 4 * q) = w;
    }
}

// --------------------------------------------------------------------------
// common PTX helpers
// --------------------------------------------------------------------------
__device__ __forceinline__ uint32_t smem_u32(const void* p) {
    uint32_t a;
    asm("{ .reg .u64 t; cvta.to.shared.u64 t, %1; cvt.u32.u64 %0, t; }"
        : "=r"(a) : "l"(p));
    return a;
}
__device__ __forceinline__ void mma16832f8(float* c, uint32_t a0, uint32_t a1,
                                           uint32_t a2, uint32_t a3,
                                           uint32_t b0, uint32_t b1) {
    asm volatile(
        "mma.sync.aligned.m16n8k32.row.col.f32.e4m3.e4m3.f32 "
        "{%0,%1,%2,%3}, {%4,%5,%6,%7}, {%8,%9}, {%0,%1,%2,%3};"
        : "+f"(c[0]), "+f"(c[1]), "+f"(c[2]), "+f"(c[3])
        : "r"(a0), "r"(a1), "r"(a2), "r"(a3), "r"(b0), "r"(b1));
}
__device__ __forceinline__ void ldsm4(uint32_t& r0, uint32_t& r1,
                                      uint32_t& r2, uint32_t& r3, uint32_t addr) {
    asm volatile("ldmatrix.sync.aligned.m8n8.x4.shared.b16 {%0,%1,%2,%3}, [%4];"
                 : "=r"(r0), "=r"(r1), "=r"(r2), "=r"(r3) : "r"(addr));
}
__device__ __forceinline__ void cp16(uint32_t saddr, const void* gptr) {
    asm volatile("cp.async.cg.shared.global [%0], [%1], 16;"
                 :: "r"(saddr), "l"(gptr));
}
#define CP_COMMIT() asm volatile("cp.async.commit_group;" ::: "memory")
#define CP_WAIT(n)  asm volatile("cp.async.wait_group %0;" :: "n"(n) : "memory")

// --------------------------------------------------------------------------
// k_gemm: I_h = A8 @ B8^T via mma.m16n8k32.e4m3, f32 accum -> fp16 out.
// CTA 128x128, 8 warps (2M x 4N, warp 64x32), 2-stage cp.async 64KB,
// 2 CTAs/SM. XOR-swizzled SMEM (128B rows) + ldmatrix.b16 (b16 = 2 fp8).
// K chunks of 128 fp8 bytes, 7 chunks.
// --------------------------------------------------------------------------
#define STB8 32768   // per stage: A 16KB + B 16KB

__global__ void __launch_bounds__(256, 2) k_gemm() {
    __shared__ __align__(16) uint8_t smbuf[2 * STB8];

    const int tid  = threadIdx.x;
    const int warp = tid >> 5, lane = tid & 31;
    const int wm = warp & 1;            // m offset 64*wm
    const int wn = warp >> 1;           // n offset 32*wn (0..3)
    const int n0 = blockIdx.x * 128;
    const int p0 = blockIdx.y * 128;
    const uint32_t sbase = smem_u32(smbuf);

    const int srow = tid >> 3;          // 0..31
    const int sc   = tid & 7;

    float acc[4][4][4];
    #pragma unroll
    for (int mt = 0; mt < 4; mt++)
        #pragma unroll
        for (int nt = 0; nt < 4; nt++)
            #pragma unroll
            for (int q = 0; q < 4; q++) acc[mt][nt][q] = 0.0f;

    auto issue = [&](int c, int s) {
        const uint32_t st0 = sbase + s * STB8;
        const size_t kof = (size_t)c * 128 + sc * 16;
        #pragma unroll
        for (int it = 0; it < 8; it++) {
            const int row = (it & 3) * 32 + srow;
            const int off = row * 128 + ((sc ^ (row & 7)) << 4);
            if (it < 4) cp16(st0 + off,         g_A8 + (size_t)(p0 + row) * KPAD8 + kof);
            else        cp16(st0 + 16384 + off, g_B8 + (size_t)(n0 + row) * KPAD8 + kof);
        }
        CP_COMMIT();
    };

    issue(0, 0);

    #pragma unroll 1
    for (int c = 0; c < NCH8; c++) {
        if (c + 1 < NCH8) {
            issue(c + 1, (c + 1) & 1);
            CP_WAIT(1);
        } else {
            CP_WAIT(0);
        }
        __syncthreads();

        const uint32_t sa = sbase + (c & 1) * STB8;
        const uint32_t sb = sa + 16384;

        #pragma unroll
        for (int ks = 0; ks < 4; ks++) {           // 4 k-steps of 32 fp8
            const int kch = ks * 2 + (lane >> 4);  // 16B chunk (0..7)
            uint32_t af[4][4];
            #pragma unroll
            for (int mt = 0; mt < 4; mt++) {
                const int r = wm * 64 + mt * 16 + (lane & 15);
                ldsm4(af[mt][0], af[mt][1], af[mt][2], af[mt][3],
                      sa + r * 128 + ((kch ^ (r & 7)) << 4));
            }
            #pragma unroll
            for (int nt2 = 0; nt2 < 2; nt2++) {
                const int r = wn * 32 + nt2 * 16 + (lane & 15);
                uint32_t b0, b1, b2, b3;
                ldsm4(b0, b1, b2, b3, sb + r * 128 + ((kch ^ (r & 7)) << 4));
                #pragma unroll
                for (int mt = 0; mt < 4; mt++) {
                    mma16832f8(acc[mt][2 * nt2],     af[mt][0], af[mt][1], af[mt][2], af[mt][3], b0, b2);
                    mma16832f8(acc[mt][2 * nt2 + 1], af[mt][0], af[mt][1], af[mt][2], af[mt][3], b1, b3);
                }
            }
        }
        __syncthreads();
    }

    // epilogue: f32 acc -> fp16 g_Ih
    __half* Ih = (__half*)g_Ih;
    #pragma unroll
    for (int mt = 0; mt < 4; mt++) {
        const int m = p0 + wm * 64 + mt * 16 + (lane >> 2);
        #pragma unroll
        for (int nt = 0; nt < 4; nt++) {
            const int n = n0 + wn * 32 + nt * 8 + (lane & 3) * 2;
            __half2 lo = __float22half2_rn(make_float2(acc[mt][nt][0], acc[mt][nt][1]));
            __half2 hi = __float22half2_rn(make_float2(acc[mt][nt][2], acc[mt][nt][3]));
            *reinterpret_cast<__half2*>(Ih + (size_t)m * NHID + n)       = lo;
            *reinterpret_cast<__half2*>(Ih + (size_t)(m + 8) * NHID + n) = hi;
        }
    }
}

// --------------------------------------------------------------------------
// k3: hidden LIF + fused output-layer neg contributions (R16 warp-private).
// --------------------------------------------------------------------------
#define LCHUNK 40
#define WBUF   (LCHUNK * 32 * 2)    // 2560 B per warp per buffer

__global__ void __launch_bounds__(128) k_lif_hidden(const float* __restrict__ w2,
                                                    float* __restrict__ hs_out) {
    __shared__ __align__(16) uint8_t sbuf[4 * 2 * WBUF];
    const int tid  = threadIdx.x;
    const int warp = tid >> 5, lane = tid & 31;
    const int bh = blockIdx.x * 128 + tid;
    const int b = bh >> 10;
    const int hw0 = (blockIdx.x & 7) * 128 + warp * 32;
    const uint32_t wbase = smem_u32(sbuf) + warp * 2 * WBUF;
    const __half* Ihg = (const __half*)g_Ih;
    float* obase = hs_out + (size_t)bh * TT;

    auto issue = [&](int chunk, int buf) {
        const uint32_t st0 = wbase + buf * WBUF;
        #pragma unroll
        for (int q = 0; q < 5; q++) {
            const int idx = lane + 32 * q;
            const int t = idx >> 2, slot = idx & 3;
            const __half* src = Ihg + (size_t)(chunk * LCHUNK + t) * (BSZ * NHID)
                                + (size_t)b * NHID + hw0 + slot * 8;
            cp16(st0 + t * 64 + slot * 16, src);
        }
        CP_COMMIT();
    };

    issue(0, 0);

    float v = 0.0f;
    #pragma unroll 1
    for (int c = 0; c < TT / LCHUNK; c++) {
        if (c + 1 < TT / LCHUNK) { issue(c + 1, (c + 1) & 1); CP_WAIT(1); }
        else                     { CP_WAIT(0); }
        __syncwarp();

        const __half* ssrc = (const __half*)(sbuf + warp * 2 * WBUF + (c & 1) * WBUF);
        const int tc = c * LCHUNK;
        float rr[LCHUNK];
        #pragma unroll
        for (int j = 0; j < LCHUNK; j++) {
            float I = __half2float(ssrc[j * 32 + lane]);
            v = __fadd_rn(__fadd_rn(v, __fmul_rn(ALPHA, -v)), I);
            float s;
            if (v >= 1.0f) { s = 1.0f; v = 0.0f; }
            else {
                s = 0.0f;
                float* pb = g_part + ((size_t)b * TT + (tc + j)) * NOUT;
                const int h = hw0 + lane;
                #pragma unroll
                for (int o = 0; o < NOUT; o++)
                    atomicAdd(pb + o, fmaxf(w2[(size_t)h * NOUT + o], 0.0f));
            }
            rr[j] = s;
        }
        #pragma unroll
        for (int q = 0; q < LCHUNK / 4; q++) {
            float4 o4 = make_float4(rr[4*q], rr[4*q+1], rr[4*q+2], rr[4*q+3]);
            *reinterpret_cast<float4*>(obase + tc + 4*q) = o4;
        }
        __syncwarp();
    }
}

// --------------------------------------------------------------------------
// k4b: output LIF + firing rates (exact R13).
// --------------------------------------------------------------------------
__global__ void k_out_lif(float* __restrict__ os_out,
                          float* __restrict__ fr_out) {
    const int gid = blockIdx.x * blockDim.x + threadIdx.x;
    if (gid >= BSZ * NOUT) return;
    const int b = gid / NOUT;
    const int o = gid - b * NOUT;

    const float colsum = g_colsum[o];
    const float* pb = g_part + (size_t)b * TT * NOUT + o;
    float v = 0.0f, cnt = 0.0f;
    float* ob = os_out + ((size_t)b * NOUT + o) * TT;

    #pragma unroll 1
    for (int tc = 0; tc < TT; tc += 10) {
        float neg[10];
        #pragma unroll
        for (int j = 0; j < 10; j++) {
            const int t = tc + j;
            neg[j] = (t > 0) ? pb[(size_t)(t - 1) * NOUT] : 0.0f;
        }
        float out[10];
        #pragma unroll
        for (int j = 0; j < 10; j++) {
            const int t = tc + j;
            float I = (t > 0) ? (colsum - neg[j]) : 0.0f;
            v = __fadd_rn(__fadd_rn(v, __fmul_rn(ALPHA, -v)), I);
            float s = (v >= 1.0f) ? 1.0f : 0.0f;
            if (v >= 1.0f) v = 0.0f;
            out[j] = s;
            cnt += s;
        }
        #pragma unroll
        for (int j = 0; j < 10; j++) ob[tc + j] = out[j];
    }
    fr_out[gid] = cnt / (float)TT;
}

// --------------------------------------------------------------------------
extern "C" void kernel_launch(void* const* d_in, const int* in_sizes, int n_in,
                              void* d_out, int out_size) {
    const float* sp = (const float*)d_in[0];   // (128, 784, 200)
    const float* w1 = (const float*)d_in[1];   // (784, 1024)
    const float* w2 = (const float*)d_in[2];   // (1024, 10)

    float* hs = (float*)d_out;                          // (B, NHID, T)
    float* os = hs + (size_t)BSZ * NHID * TT;           // (B, NOUT, T)
    float* fr = os + (size_t)BSZ * NOUT * TT;           // (B, NOUT)

    kA_stage<<<dim3(BSZ, 7), 256>>>(sp);
    kB_stage<<<dim3(32, 8), 256>>>(w1, w2);
    k_gemm<<<dim3(NHID / 128, NPAIR / 128), 256>>>();
    k_lif_hidden<<<(BSZ * NHID) / 128, 128>>>(w2, hs);
    k_out_lif<<<5, 256>>>(os, fr);
}